// round 3
// baseline (speedup 1.0000x reference)
#include <cuda_runtime.h>
#include <cuda_bf16.h>

#define NPTS   65536
#define CHN    256
#define BATCH  16
#define LOUT   8192
#define LOG2L  13

// g_off[b] = first index with batch id >= b; g_off[BATCH] = NPTS.
__device__ int g_off[BATCH + 1];

// ------------------------------------------------------- boundary detect ---
// batch is sorted. One thread per element, fully coalesced, no atomics.
__global__ void boundary_kernel(const int* __restrict__ batch) {
    int i = blockIdx.x * blockDim.x + threadIdx.x;
    if (i >= NPTS) return;
    int cur  = batch[i];
    int prev = (i == 0) ? -1 : batch[i - 1];
    for (int bb = prev + 1; bb <= cur; bb++) g_off[bb] = i;
    if (i == NPTS - 1) {
        for (int bb = cur + 1; bb <= BATCH; bb++) g_off[bb] = NPTS;
    }
}

// --------------------------------------------------------- fused gather ----
// 1D grid: blocks [0,128)   -> points gather  (16*8192/4 threads of work)
//          blocks [128,8320)-> feature gather-transpose, 128(j) x 32(c) tile.
#define PT_BLOCKS 128
#define TJ 128
#define TC 32

__global__ __launch_bounds__(256)
void fused_kernel(const float* __restrict__ px,
                  const float4* __restrict__ feat4,
                  float* __restrict__ out_point,
                  float* __restrict__ out_feat) {
    int bid = blockIdx.x;
    int tid = threadIdx.x;

    if (bid < PT_BLOCKS) {
        // ---- points: thread handles 4 consecutive j of one (b); float4 writes
        int idx = bid * 256 + tid;              // 0 .. B*L/4-1
        int j = (idx & (LOUT / 4 - 1)) * 4;
        int b = idx >> (LOG2L - 2);
        int off = g_off[b];
        int cnt = g_off[b + 1] - off;
        float4 ox, oy, oz;
        #pragma unroll
        for (int t = 0; t < 4; t++) {
            int src = off + (int)(((unsigned)((j + t) * cnt)) >> LOG2L);
            const float* p = px + 3 * src;
            ((float*)&ox)[t] = p[0];
            ((float*)&oy)[t] = p[1];
            ((float*)&oz)[t] = p[2];
        }
        size_t base = (size_t)b * 3 * LOUT + j;
        *(float4*)(out_point + base)            = ox;
        *(float4*)(out_point + base + LOUT)     = oy;
        *(float4*)(out_point + base + 2 * LOUT) = oz;
        return;
    }

    // ---- features ----
    __shared__ float tile[TJ][TC + 1];
    __shared__ int   s_src[TJ];

    int fb = bid - PT_BLOCKS;                 // 0 .. 8191
    int j0 = (fb & 63) << 7;                  // 64 j-tiles of 128
    int c0 = ((fb >> 6) & 7) << 5;            // 8 channel-tiles of 32
    int b  = fb >> 9;                         // 16 batches

    if (tid < TJ) {
        int off = g_off[b];
        int cnt = g_off[b + 1] - off;
        int j = j0 + tid;
        s_src[tid] = off + (int)(((unsigned)(j * cnt)) >> LOG2L);
    }
    __syncthreads();

    // Load: 4x LDG.128 per thread; 8 lanes cover 128B of one feature row.
    // STS banks = row + 4*c4 + i -> conflict-free.
    int c4base = c0 >> 2;
    #pragma unroll
    for (int k = 0; k < 4; k++) {
        int idx = tid + k * 256;
        int row = idx >> 3;                   // 0..127
        int c4  = idx & 7;                    // 0..7
        float4 v = feat4[(size_t)s_src[row] * (CHN / 4) + c4base + c4];
        tile[row][c4 * 4 + 0] = v.x;
        tile[row][c4 * 4 + 1] = v.y;
        tile[row][c4 * 4 + 2] = v.z;
        tile[row][c4 * 4 + 3] = v.w;
    }
    __syncthreads();

    // Store: warp owns 4 channels. Lane L writes j = 4L..4L+3 as one STG.128.
    // Rotated-row LDS schedule: step i reads row 4L + ((L>>3)+i)&3 ->
    // bank = 4*(L&7) + ((L>>3)+i)&3 + c covers all 32 banks: conflict-free.
    int L = tid & 31;
    int w = tid >> 5;                         // 0..7
    int rot = L >> 3;                         // 0..3
    #pragma unroll
    for (int k = 0; k < 4; k++) {
        int c = w * 4 + k;                    // 0..31
        float4 v;
        #pragma unroll
        for (int i = 0; i < 4; i++) {
            int d = (rot + i) & 3;            // component index
            ((float*)&v)[d] = tile[4 * L + d][c];
        }
        *(float4*)(out_feat + (size_t)(b * CHN + c0 + c) * LOUT + j0 + 4 * L) = v;
    }
}

// ------------------------------------------------------------- launch ------
extern "C" void kernel_launch(void* const* d_in, const int* in_sizes, int n_in,
                              void* d_out, int out_size) {
    const float* points_x = (const float*)d_in[0];   // [N,3]
    const float* feat     = (const float*)d_in[1];   // [N,C]
    const int*   batch    = (const int*)d_in[2];     // [N]

    float* out_point = (float*)d_out;                              // [B,3,L]
    float* out_feat  = (float*)d_out + (size_t)BATCH * 3 * LOUT;   // [B,C,L]

    boundary_kernel<<<NPTS / 256, 256>>>(batch);

    int nblocks = PT_BLOCKS + (LOUT / TJ) * (CHN / TC) * BATCH;    // 128 + 8192
    fused_kernel<<<nblocks, 256>>>(points_x, (const float4*)feat,
                                   out_point, out_feat);
}